// round 1
// baseline (speedup 1.0000x reference)
#include <cuda_runtime.h>

// Problem constants (fixed by the reference): B=2048, F=40, E=64, I=780
#define FDIM   40
#define EDIM   64
#define NPAIR  780          // F*(F-1)/2
#define BT     8            // batches per block
#define E4     (EDIM / 4)   // 16 float4 chunks per row
#define ROWSTRIDE 68        // smem floats per field row (64 + 4 pad -> conflict-free)
#define BSTRIDE   (FDIM * ROWSTRIDE)   // 2720 floats per batch in smem

// Scratch for the kernel-sum (sum over axis 0 of the (E, I, E) kernel tensor)
__device__ float g_ksum[NPAIR * EDIM];

// ---------------------------------------------------------------------------
// Kernel 1: ksum[p][e] = sum_k kernel[k][p][e]   (kernel is (E, I, E) row-major)
// ---------------------------------------------------------------------------
__global__ void ksum_kernel(const float* __restrict__ kern)
{
    const int n4 = NPAIR * EDIM / 4;          // 12480 float4 elements
    int idx4 = blockIdx.x * blockDim.x + threadIdx.x;
    if (idx4 >= n4) return;

    const float4* k4 = reinterpret_cast<const float4*>(kern);
    float4 s = make_float4(0.f, 0.f, 0.f, 0.f);
    #pragma unroll 8
    for (int k = 0; k < EDIM; ++k) {
        float4 v = k4[(size_t)k * n4 + idx4];
        s.x += v.x; s.y += v.y; s.z += v.z; s.w += v.w;
    }
    reinterpret_cast<float4*>(g_ksum)[idx4] = s;
}

// ---------------------------------------------------------------------------
// Kernel 2: out[b][p] = sum_e A[b][i_p][e] * ksum[p][e] * A[b][j_p][e]
// One block = BT batches (staged in smem) x all 780 pairs.
// ---------------------------------------------------------------------------
__global__ void __launch_bounds__(256, 2) interact_kernel(
    const float* __restrict__ A,   // (B, F, E) row-major
    float*       __restrict__ out) // (B, NPAIR) row-major
{
    extern __shared__ float smem[];
    float* sA = smem;                                   // BT * BSTRIDE floats
    unsigned char* spi = (unsigned char*)(smem + BT * BSTRIDE);
    unsigned char* spj = spi + 800;                     // padded to keep alignment

    const int tid = threadIdx.x;
    const int b0  = blockIdx.x * BT;

    // ---- build pair index table (i, j) for p = 0..779 ----
    for (int p = tid; p < NPAIR; p += 256) {
        int i = 0, cum = 0;
        while (cum + (FDIM - 1 - i) <= p) { cum += FDIM - 1 - i; ++i; }
        int j = i + 1 + (p - cum);
        spi[p] = (unsigned char)i;
        spj[p] = (unsigned char)j;
    }

    // ---- stage BT batches of A into padded smem (float4 loads) ----
    const float4* A4 = reinterpret_cast<const float4*>(A);
    for (int v = tid; v < BT * FDIM * E4; v += 256) {
        int b  = v / (FDIM * E4);
        int r  = v % (FDIM * E4);
        int f  = r / E4;
        int e4 = r % E4;
        float4 val = A4[(size_t)(b0 + b) * (FDIM * E4) + f * E4 + e4];
        *reinterpret_cast<float4*>(&sA[b * BSTRIDE + f * ROWSTRIDE + e4 * 4]) = val;
    }
    __syncthreads();

    // ---- main loop: each thread owns pairs tid, tid+256, ... ----
    const float4* w4 = reinterpret_cast<const float4*>(g_ksum);
    for (int p = tid; p < NPAIR; p += 256) {
        const int ibase = spi[p] * ROWSTRIDE;
        const int jbase = spj[p] * ROWSTRIDE;

        float acc[BT];
        #pragma unroll
        for (int b = 0; b < BT; ++b) acc[b] = 0.f;

        #pragma unroll 4
        for (int e4 = 0; e4 < E4; ++e4) {
            const float4 w = w4[p * E4 + e4];   // L2-resident (200 KB total)
            const int eo = e4 * 4;
            #pragma unroll
            for (int b = 0; b < BT; ++b) {
                const float* base = &sA[b * BSTRIDE];
                float4 xi = *reinterpret_cast<const float4*>(&base[ibase + eo]);
                float4 xj = *reinterpret_cast<const float4*>(&base[jbase + eo]);
                float a = acc[b];
                a = fmaf(w.x * xi.x, xj.x, a);
                a = fmaf(w.y * xi.y, xj.y, a);
                a = fmaf(w.z * xi.z, xj.z, a);
                a = fmaf(w.w * xi.w, xj.w, a);
                acc[b] = a;
            }
        }

        #pragma unroll
        for (int b = 0; b < BT; ++b)
            out[(size_t)(b0 + b) * NPAIR + p] = acc[b];
    }
}

// ---------------------------------------------------------------------------
// Launch
// ---------------------------------------------------------------------------
extern "C" void kernel_launch(void* const* d_in, const int* in_sizes, int n_in,
                              void* d_out, int out_size)
{
    const float* inputs = (const float*)d_in[0];   // (B, F, E) float32
    const float* kern   = (const float*)d_in[1];   // (E, I, E) float32
    (void)n_in; (void)out_size;

    const int B = in_sizes[0] / (FDIM * EDIM);     // 2048

    const size_t smem_bytes = (size_t)BT * BSTRIDE * sizeof(float) + 1600;
    cudaFuncSetAttribute(interact_kernel,
                         cudaFuncAttributeMaxDynamicSharedMemorySize,
                         (int)smem_bytes);

    // 1) reduce kernel tensor over axis 0
    {
        const int n4 = NPAIR * EDIM / 4;
        ksum_kernel<<<(n4 + 255) / 256, 256>>>(kern);
    }
    // 2) pairwise interactions
    interact_kernel<<<B / BT, 256, smem_bytes>>>(inputs, (float*)d_out);
}